// round 1
// baseline (speedup 1.0000x reference)
#include <cuda_runtime.h>
#include <math.h>

#define Bn 4
#define Cc 192
#define Dd 4
#define Hh 16
#define Ww 16
#define LL 1024           // Dd*Hh*Ww
#define DIN 384
#define DSTATE 64
#define DTRANK 12
#define DCONV 4

// ---------------- scratch (device globals; no allocation) ----------------
__device__ float g_pooled[Bn * Cc];
__device__ float g_wts[Bn * 3];
__device__ float g_hid[Bn * 48 * LL];
__device__ float g_offs[Bn * LL * 3];
__device__ float g_xs[Bn * LL * Cc];
__device__ float g_xz[Bn * LL * 2 * DIN];
__device__ float g_xi[Bn * LL * DIN];
__device__ float g_dbl[Bn * LL * 140];
__device__ float g_delta[Bn * LL * DIN];
__device__ float g_A[DIN * DSTATE];
__device__ float g_y[Bn * LL * DIN];
__device__ float g_p2[Bn * Cc];
__device__ float g_attn[Bn * Cc];

__device__ __forceinline__ float sigmoidf_(float x) { return 1.f / (1.f + expf(-x)); }
__device__ __forceinline__ float geluf_(float x) {
    return 0.5f * x * (1.f + erff(x * 0.70710678118654752440f));
}
__device__ __forceinline__ float softplusf_(float x) {
    return (x > 20.f) ? x : log1pf(expf(x));
}

// ---------------- mean over last dim (1024) : in [N,1024] -> out[N]/1024 ----------------
__global__ void mean_kernel(const float* __restrict__ in, float* __restrict__ out) {
    int bc = blockIdx.x;
    const float* p = in + bc * LL;
    float s = 0.f;
    for (int i = threadIdx.x; i < LL; i += 256) s += p[i];
    __shared__ float sm[256];
    sm[threadIdx.x] = s; __syncthreads();
    for (int st = 128; st > 0; st >>= 1) {
        if (threadIdx.x < st) sm[threadIdx.x] += sm[threadIdx.x + st];
        __syncthreads();
    }
    if (threadIdx.x == 0) out[bc] = sm[0] * (1.f / (float)LL);
}

// ---------------- branch gate weights: softmax(pooled @ wg_w.T + wg_b) ----------------
__global__ void wts_kernel(const float* __restrict__ wg_w, const float* __restrict__ wg_b) {
    int b = blockIdx.x;
    int i = threadIdx.x >> 5;      // 0..2
    int lane = threadIdx.x & 31;
    float s = 0.f;
    for (int c = lane; c < Cc; c += 32) s += g_pooled[b * Cc + c] * wg_w[i * Cc + c];
    for (int off = 16; off; off >>= 1) s += __shfl_xor_sync(0xffffffffu, s, off);
    __shared__ float lg[3];
    if (lane == 0) lg[i] = s + wg_b[i];
    __syncthreads();
    if (threadIdx.x == 0) {
        float m = fmaxf(lg[0], fmaxf(lg[1], lg[2]));
        float e0 = expf(lg[0] - m), e1 = expf(lg[1] - m), e2 = expf(lg[2] - m);
        float inv = 1.f / (e0 + e1 + e2);
        g_wts[b * 3 + 0] = e0 * inv;
        g_wts[b * 3 + 1] = e1 * inv;
        g_wts[b * 3 + 2] = e2 * inv;
    }
}

// ---------------- offset conv layer 1 : [B,192,D,H,W] -> gelu -> [B,48,D,H,W] ----------------
// one block per (b, voxel); blockDim = 192 (48 outputs x 4 c-partitions)
__global__ void conv1_kernel(const float* __restrict__ x, const float* __restrict__ w1,
                             const float* __restrict__ b1) {
    int bv = blockIdx.x;
    int b = bv >> 10, v = bv & 1023;
    int z = v >> 8, y = (v >> 4) & 15, xx = v & 15;
    __shared__ float xn[96 * 27];
    __shared__ float red[192];
    int tid = threadIdx.x;
    int o = tid % 48, q = tid / 48;
    float acc = 0.f;
    for (int cc = 0; cc < Cc; cc += 96) {
        for (int idx = tid; idx < 96 * 27; idx += 192) {
            int c = cc + idx / 27; int tap = idx % 27;
            int kd = tap / 9, kh = (tap / 3) % 3, kw = tap % 3;
            int zz = z + kd - 1, yy = y + kh - 1, xw = xx + kw - 1;
            float val = 0.f;
            if (zz >= 0 && zz < Dd && yy >= 0 && yy < Hh && xw >= 0 && xw < Ww)
                val = x[(b * Cc + c) * LL + zz * 256 + yy * 16 + xw];
            xn[idx] = val;
        }
        __syncthreads();
        const float* wbase = w1 + (o * Cc + cc) * 27;
        for (int cl = q * 24; cl < q * 24 + 24; ++cl) {
            #pragma unroll
            for (int tap = 0; tap < 27; ++tap)
                acc += xn[cl * 27 + tap] * wbase[cl * 27 + tap];
        }
        __syncthreads();
    }
    red[tid] = acc; __syncthreads();
    if (q == 0) {
        float s = red[o] + red[48 + o] + red[96 + o] + red[144 + o] + b1[o];
        g_hid[(b * 48 + o) * LL + v] = geluf_(s);
    }
}

// ---------------- offset conv layer 2 : [B,48,D,H,W] -> [B,L,3] (channels-last) ----------------
// one block per (b, voxel); blockDim = 144 (3 outputs x 48 inputs)
__global__ void conv2_kernel(const float* __restrict__ w2, const float* __restrict__ b2) {
    int bv = blockIdx.x;
    int b = bv >> 10, v = bv & 1023;
    int z = v >> 8, y = (v >> 4) & 15, xx = v & 15;
    int tid = threadIdx.x;
    int j = tid / 48, i = tid % 48;
    const float* hb = g_hid + (b * 48 + i) * LL;
    const float* wb = w2 + (j * 48 + i) * 27;
    float acc = 0.f;
    #pragma unroll
    for (int tap = 0; tap < 27; ++tap) {
        int kd = tap / 9, kh = (tap / 3) % 3, kw = tap % 3;
        int zz = z + kd - 1, yy = y + kh - 1, xw = xx + kw - 1;
        if (zz >= 0 && zz < Dd && yy >= 0 && yy < Hh && xw >= 0 && xw < Ww)
            acc += hb[zz * 256 + yy * 16 + xw] * wb[tap];
    }
    __shared__ float red[144];
    red[tid] = acc; __syncthreads();
    if (tid < 3) {
        float s = b2[tid];
        for (int k = 0; k < 48; ++k) s += red[tid * 48 + k];
        g_offs[bv * 3 + tid] = s;
    }
}

// ---------------- x_seq (tri-branch proj) + deformable pos-emb (grid sample) ----------------
// block per (b,l); blockDim = 192 (one out-channel each)
__global__ void xseq_kernel(const float* __restrict__ x,
                            const float* __restrict__ px_w, const float* __restrict__ px_b,
                            const float* __restrict__ py_w, const float* __restrict__ py_b,
                            const float* __restrict__ pz_w, const float* __restrict__ pz_b) {
    int bl = blockIdx.x;
    int b = bl >> 10, l = bl & 1023;
    int c = threadIdx.x;
    __shared__ float xr[Cc];
    xr[c] = x[(b * Cc + c) * LL + l];
    __syncthreads();
    int i = c / 64, oo = c % 64;
    const float* pw = (i == 0) ? px_w : (i == 1) ? py_w : pz_w;
    const float* pb = (i == 0) ? px_b : (i == 1) ? py_b : pz_b;
    const float* wrow = pw + oo * Cc;
    float s = 0.f;
    #pragma unroll 8
    for (int k = 0; k < Cc; ++k) s += xr[k] * wrow[k];
    s = (s + pb[oo]) * g_wts[b * 3 + i];

    // grid sample (align_corners=False, zero padding)
    float gx = g_offs[bl * 3 + 0];
    float gy = g_offs[bl * 3 + 1];
    float gz = g_offs[bl * 3 + 2];
    float ixf = ((gx + 1.f) * (float)Ww - 1.f) * 0.5f;
    float iyf = ((gy + 1.f) * (float)Hh - 1.f) * 0.5f;
    float izf = ((gz + 1.f) * (float)Dd - 1.f) * 0.5f;
    float x0 = floorf(ixf), y0 = floorf(iyf), z0 = floorf(izf);
    const float* vb = x + (b * Cc + c) * LL;
    float pe = 0.f;
    #pragma unroll
    for (int dz = 0; dz < 2; ++dz)
    #pragma unroll
    for (int dy = 0; dy < 2; ++dy)
    #pragma unroll
    for (int dx = 0; dx < 2; ++dx) {
        float xc = x0 + dx, yc = y0 + dy, zc = z0 + dz;
        float wgt = (1.f - fabsf(ixf - xc)) * (1.f - fabsf(iyf - yc)) * (1.f - fabsf(izf - zc));
        bool valid = (xc >= 0.f) && (xc < (float)Ww) && (yc >= 0.f) && (yc < (float)Hh)
                  && (zc >= 0.f) && (zc < (float)Dd);
        int xi_ = (int)fminf(fmaxf(xc, 0.f), (float)(Ww - 1));
        int yi_ = (int)fminf(fmaxf(yc, 0.f), (float)(Hh - 1));
        int zi_ = (int)fminf(fmaxf(zc, 0.f), (float)(Dd - 1));
        int idx = (zi_ * Hh + yi_) * Ww + xi_;
        pe += vb[idx] * wgt * (valid ? 1.f : 0.f);
    }
    g_xs[bl * Cc + c] = s + pe;
}

// ---------------- in_proj : [B,L,192] @ [768,192]^T -> [B,L,768] ----------------
// block per (b,l); blockDim = 256, 3 outputs per thread
__global__ void inproj_kernel(const float* __restrict__ w) {
    int bl = blockIdx.x;
    int tid = threadIdx.x;
    __shared__ float xr[Cc];
    for (int k = tid; k < Cc; k += 256) xr[k] = g_xs[bl * Cc + k];
    __syncthreads();
    const float* w0 = w + (tid) * Cc;
    const float* w1 = w + (tid + 256) * Cc;
    const float* w2 = w + (tid + 512) * Cc;
    float a0 = 0.f, a1 = 0.f, a2 = 0.f;
    #pragma unroll 4
    for (int k = 0; k < Cc; ++k) {
        float xv = xr[k];
        a0 += xv * w0[k]; a1 += xv * w1[k]; a2 += xv * w2[k];
    }
    float* out = g_xz + bl * (2 * DIN);
    out[tid] = a0; out[tid + 256] = a1; out[tid + 512] = a2;
}

// ---------------- depthwise causal conv (k=4) + silu : xz[:,:384] -> xi ----------------
__global__ void dwconv_kernel(const float* __restrict__ cw, const float* __restrict__ cb) {
    int t = blockIdx.x * blockDim.x + threadIdx.x;
    if (t >= Bn * LL * DIN) return;
    int d = t % DIN; int bl = t / DIN; int l = bl % LL; int b = bl / LL;
    const float* base = g_xz + (b * LL) * (2 * DIN) + d;
    float s = cb[d];
    #pragma unroll
    for (int k = 0; k < DCONV; ++k) {
        int ll = l - (DCONV - 1) + k;
        if (ll >= 0) s += base[ll * (2 * DIN)] * cw[d * DCONV + k];
    }
    g_xi[t] = s * sigmoidf_(s);
}

// ---------------- x_proj : xi[B,L,384] @ [140,384]^T -> dbl [B,L,140] ----------------
__global__ void xproj_kernel(const float* __restrict__ w) {
    int bl = blockIdx.x;
    int tid = threadIdx.x;   // 160
    __shared__ float xr[DIN];
    for (int k = tid; k < DIN; k += 160) xr[k] = g_xi[bl * DIN + k];
    __syncthreads();
    if (tid < 140) {
        const float* wr = w + tid * DIN;
        float s = 0.f;
        #pragma unroll 8
        for (int k = 0; k < DIN; ++k) s += xr[k] * wr[k];
        g_dbl[bl * 140 + tid] = s;
    }
}

// ---------------- delta = softplus(dt @ dt_proj_w.T + dt_proj_b) ----------------
__global__ void delta_kernel(const float* __restrict__ dtw, const float* __restrict__ dtb) {
    int t = blockIdx.x * blockDim.x + threadIdx.x;
    if (t >= Bn * LL * DIN) return;
    int d = t % DIN; int bl = t / DIN;
    const float* row = g_dbl + bl * 140;
    const float* wr = dtw + d * DTRANK;
    float s = dtb[d];
    #pragma unroll
    for (int r = 0; r < DTRANK; ++r) s += row[r] * wr[r];
    g_delta[t] = softplusf_(s);
}

// ---------------- A = -exp(A_log) ----------------
__global__ void a_kernel(const float* __restrict__ a_log) {
    int t = blockIdx.x * blockDim.x + threadIdx.x;
    if (t < DIN * DSTATE) g_A[t] = -expf(a_log[t]);
}

// ---------------- selective scan + silu(z) gate : one warp per (b,d) ----------------
__global__ void scan_kernel(const float* __restrict__ Dskip) {
    int warp = (blockIdx.x * blockDim.x + threadIdx.x) >> 5;
    int lane = threadIdx.x & 31;
    if (warp >= Bn * DIN) return;
    int b = warp / DIN, d = warp % DIN;
    float a0 = g_A[d * DSTATE + lane];
    float a1 = g_A[d * DSTATE + 32 + lane];
    float dsk = Dskip[d];
    float h0 = 0.f, h1 = 0.f;
    const float* dptr = g_delta + b * LL * DIN + d;
    const float* uptr = g_xi + b * LL * DIN + d;
    const float* dblb = g_dbl + b * LL * 140;
    const float* zptr = g_xz + b * LL * (2 * DIN) + DIN + d;
    float* yo = g_y + b * LL * DIN + d;
    for (int l = 0; l < LL; ++l) {
        float dt = dptr[l * DIN];
        float u = uptr[l * DIN];
        const float* row = dblb + l * 140;
        float b0 = row[12 + lane], b1 = row[44 + lane];
        float c0 = row[76 + lane], c1 = row[108 + lane];
        float du = dt * u;
        h0 = expf(dt * a0) * h0 + du * b0;
        h1 = expf(dt * a1) * h1 + du * b1;
        float part = h0 * c0 + h1 * c1;
        #pragma unroll
        for (int off = 16; off; off >>= 1) part += __shfl_xor_sync(0xffffffffu, part, off);
        if (lane == 0) {
            float z = zptr[l * (2 * DIN)];
            yo[l * DIN] = (part + u * dsk) * (z * sigmoidf_(z));
        }
    }
}

// ---------------- out_proj : y[B,L,384] @ [192,384]^T -> feat -> d_out [B,C,L] ----------------
__global__ void outproj_kernel(const float* __restrict__ w, float* __restrict__ out) {
    int bl = blockIdx.x;
    int b = bl >> 10, l = bl & 1023;
    int c = threadIdx.x; // 192
    __shared__ float yr[DIN];
    for (int k = c; k < DIN; k += 192) yr[k] = g_y[bl * DIN + k];
    __syncthreads();
    const float* wr = w + c * DIN;
    float s = 0.f;
    #pragma unroll 8
    for (int k = 0; k < DIN; ++k) s += yr[k] * wr[k];
    out[(b * Cc + c) * LL + l] = s;
}

// ---------------- channel attention weights ----------------
__global__ void ca_kernel(const float* __restrict__ w1, const float* __restrict__ b1,
                          const float* __restrict__ w2, const float* __restrict__ b2) {
    int b = blockIdx.x;
    int tid = threadIdx.x; // 192
    __shared__ float p[Cc];
    __shared__ float hid[48];
    p[tid] = g_p2[b * Cc + tid];
    __syncthreads();
    if (tid < 48) {
        const float* wr = w1 + tid * Cc;
        float s = b1[tid];
        for (int k = 0; k < Cc; ++k) s += p[k] * wr[k];
        hid[tid] = geluf_(s);
    }
    __syncthreads();
    const float* wr2 = w2 + tid * 48;
    float s = b2[tid];
    #pragma unroll
    for (int j = 0; j < 48; ++j) s += hid[j] * wr2[j];
    g_attn[b * Cc + tid] = sigmoidf_(s);
}

// ---------------- scale output in place ----------------
__global__ void scale_kernel(float* __restrict__ out) {
    int t = blockIdx.x * blockDim.x + threadIdx.x;
    if (t >= Bn * Cc * LL) return;
    int bc = t / LL;
    out[t] *= g_attn[bc];
}

extern "C" void kernel_launch(void* const* d_in, const int* in_sizes, int n_in,
                              void* d_out, int out_size) {
    const float* x        = (const float*)d_in[0];
    const float* px_w     = (const float*)d_in[1];
    const float* px_b     = (const float*)d_in[2];
    const float* py_w     = (const float*)d_in[3];
    const float* py_b     = (const float*)d_in[4];
    const float* pz_w     = (const float*)d_in[5];
    const float* pz_b     = (const float*)d_in[6];
    const float* wg_w     = (const float*)d_in[7];
    const float* wg_b     = (const float*)d_in[8];
    const float* off_w1   = (const float*)d_in[9];
    const float* off_b1   = (const float*)d_in[10];
    const float* off_w2   = (const float*)d_in[11];
    const float* off_b2   = (const float*)d_in[12];
    const float* in_proj_w = (const float*)d_in[13];
    const float* conv_w   = (const float*)d_in[14];
    const float* conv_b   = (const float*)d_in[15];
    const float* x_proj_w = (const float*)d_in[16];
    const float* dt_proj_w = (const float*)d_in[17];
    const float* dt_proj_b = (const float*)d_in[18];
    const float* A_log    = (const float*)d_in[19];
    const float* D_skip   = (const float*)d_in[20];
    const float* out_proj_w = (const float*)d_in[21];
    const float* ca_w1    = (const float*)d_in[22];
    const float* ca_b1    = (const float*)d_in[23];
    const float* ca_w2    = (const float*)d_in[24];
    const float* ca_b2    = (const float*)d_in[25];
    float* out = (float*)d_out;

    float* g_pooled_p; cudaGetSymbolAddress((void**)&g_pooled_p, g_pooled);
    float* g_p2_p;     cudaGetSymbolAddress((void**)&g_p2_p, g_p2);

    mean_kernel<<<Bn * Cc, 256>>>(x, g_pooled_p);
    wts_kernel<<<Bn, 96>>>(wg_w, wg_b);
    conv1_kernel<<<Bn * LL, 192>>>(x, off_w1, off_b1);
    conv2_kernel<<<Bn * LL, 144>>>(off_w2, off_b2);
    xseq_kernel<<<Bn * LL, 192>>>(x, px_w, px_b, py_w, py_b, pz_w, pz_b);
    inproj_kernel<<<Bn * LL, 256>>>(in_proj_w);
    dwconv_kernel<<<(Bn * LL * DIN + 255) / 256, 256>>>(conv_w, conv_b);
    xproj_kernel<<<Bn * LL, 160>>>(x_proj_w);
    delta_kernel<<<(Bn * LL * DIN + 255) / 256, 256>>>(dt_proj_w, dt_proj_b);
    a_kernel<<<(DIN * DSTATE + 255) / 256, 256>>>(A_log);
    scan_kernel<<<(Bn * DIN * 32 + 127) / 128, 128>>>(D_skip);
    outproj_kernel<<<Bn * LL, 192>>>(out_proj_w, out);
    mean_kernel<<<Bn * Cc, 256>>>(out, g_p2_p);
    ca_kernel<<<Bn, 192>>>(ca_w1, ca_b1, ca_w2, ca_b2);
    scale_kernel<<<(Bn * Cc * LL + 255) / 256, 256>>>(out);
}

// round 2
// speedup vs baseline: 6.9092x; 6.9092x over previous
#include <cuda_runtime.h>
#include <math.h>

#define Bn 4
#define Cc 192
#define Dd 4
#define Hh 16
#define Ww 16
#define LL 1024
#define DIN 384
#define DSTATE 64
#define DTRANK 12
#define DCONV 4
#define MM (Bn * LL)    // 4096 rows

// ---------------- scratch (device globals; no allocation) ----------------
__device__ float g_pooled[Bn * Cc];
__device__ float g_wts[Bn * 3];
__device__ float g_hid[Bn * 48 * LL];
__device__ float g_offs[Bn * LL * 3];
__device__ float g_xs[MM * Cc];
__device__ float g_xz[MM * 2 * DIN];
__device__ float g_xi[MM * DIN];
__device__ float g_dbl[MM * 140];
__device__ float g_delta[MM * DIN];
__device__ float g_A[DIN * DSTATE];
__device__ float g_y[MM * DIN];
__device__ float g_p2[Bn * Cc];
__device__ float g_attn[Bn * Cc];
__device__ float g_xT[MM * Cc];          // [b*L + l][c]
__device__ float g_Wcat[Cc * Cc];        // concat px/py/pz weights [192][192]
__device__ float g_bcat[Cc];
__device__ float g_w1t[27 * 48 * Cc];    // [tap][o][c]

__device__ __forceinline__ float sigmoidf_(float x) { return 1.f / (1.f + expf(-x)); }
__device__ __forceinline__ float geluf_(float x) {
    return 0.5f * x * (1.f + erff(x * 0.70710678118654752440f));
}
__device__ __forceinline__ float softplusf_(float x) {
    return (x > 20.f) ? x : log1pf(expf(x));
}

// ---------------- transpose x: [b][c][l] -> g_xT [b*L+l][c] ----------------
__global__ void xt_kernel(const float* __restrict__ x) {
    int t = blockIdx.x * 256 + threadIdx.x;
    if (t >= MM * Cc) return;
    int c = t % Cc;
    int bl = t / Cc;
    int b = bl >> 10, l = bl & 1023;
    g_xT[t] = x[(b * Cc + c) * LL + l];
}

// ---------------- mean over last dim (1024) ----------------
__global__ void mean_kernel(const float* __restrict__ in, float* __restrict__ out) {
    int bc = blockIdx.x;
    const float* p = in + bc * LL;
    float s = 0.f;
    for (int i = threadIdx.x; i < LL; i += 256) s += p[i];
    __shared__ float sm[256];
    sm[threadIdx.x] = s; __syncthreads();
    for (int st = 128; st > 0; st >>= 1) {
        if (threadIdx.x < st) sm[threadIdx.x] += sm[threadIdx.x + st];
        __syncthreads();
    }
    if (threadIdx.x == 0) out[bc] = sm[0] * (1.f / (float)LL);
}

// ---------------- branch gate weights ----------------
__global__ void wts_kernel(const float* __restrict__ wg_w, const float* __restrict__ wg_b) {
    int b = blockIdx.x;
    int i = threadIdx.x >> 5;
    int lane = threadIdx.x & 31;
    float s = 0.f;
    for (int c = lane; c < Cc; c += 32) s += g_pooled[b * Cc + c] * wg_w[i * Cc + c];
    for (int off = 16; off; off >>= 1) s += __shfl_xor_sync(0xffffffffu, s, off);
    __shared__ float lg[3];
    if (lane == 0) lg[i] = s + wg_b[i];
    __syncthreads();
    if (threadIdx.x == 0) {
        float m = fmaxf(lg[0], fmaxf(lg[1], lg[2]));
        float e0 = expf(lg[0] - m), e1 = expf(lg[1] - m), e2 = expf(lg[2] - m);
        float inv = 1.f / (e0 + e1 + e2);
        g_wts[b * 3 + 0] = e0 * inv;
        g_wts[b * 3 + 1] = e1 * inv;
        g_wts[b * 3 + 2] = e2 * inv;
    }
}

// ---------------- build Wcat / bcat ----------------
__global__ void catw_kernel(const float* __restrict__ px_w, const float* __restrict__ px_b,
                            const float* __restrict__ py_w, const float* __restrict__ py_b,
                            const float* __restrict__ pz_w, const float* __restrict__ pz_b) {
    int t = blockIdx.x * 256 + threadIdx.x;
    if (t < Cc * Cc) {
        int o = t / Cc, c = t % Cc;
        const float* src = (o < 64) ? px_w : (o < 128) ? py_w : pz_w;
        g_Wcat[t] = src[(o & 63) * Cc + c];
    }
    if (t < Cc) {
        const float* sb = (t < 64) ? px_b : (t < 128) ? py_b : pz_b;
        g_bcat[t] = sb[t & 63];
    }
}

// ---------------- transpose conv1 weights: [o][c][tap] -> [tap][o][c] ----------------
__global__ void w1t_kernel(const float* __restrict__ w1) {
    int t = blockIdx.x * 256 + threadIdx.x;
    if (t >= 27 * 48 * Cc) return;
    int tap = t / (48 * Cc);
    int rest = t % (48 * Cc);
    int o = rest / Cc, c = rest % Cc;
    g_w1t[t] = w1[(o * Cc + c) * 27 + tap];
}

// ---------------- conv1 tiled: x [B,192,D,H,W] -> gelu -> g_hid [B,48,L] ----------------
// grid 128 = (b(4), z(4), ypair(8)); block 128; 32 voxels x 48 outputs per block
__global__ void conv1_kernel(const float* __restrict__ x, const float* __restrict__ b1) {
    __shared__ float sA[32][97];
    __shared__ float sW[48][97];
    int bid = blockIdx.x;
    int b = bid >> 5, z = (bid >> 3) & 3, y0 = (bid & 7) * 2;
    int tid = threadIdx.x;
    int lg = tid & 7, og = tid >> 3;     // lg: 8 voxel groups of 4; og: 16 out groups of 3
    float acc[4][3] = {};
    for (int tap = 0; tap < 27; ++tap) {
        int kd = tap / 9, kh = (tap / 3) % 3, kw = tap % 3;
        int zz = z + kd - 1;
        bool zok = (zz >= 0) && (zz < Dd);
        for (int c0 = 0; c0 < Cc; c0 += 96) {
            #pragma unroll
            for (int t = 0; t < 24; ++t) {
                int idx = tid + t * 128;         // 0..3071
                int v = idx & 31, c = idx >> 5;  // c 0..95
                int vy = y0 + (v >> 4), vx = v & 15;
                int yy = vy + kh - 1, xx = vx + kw - 1;
                float val = 0.f;
                if (zok && yy >= 0 && yy < Hh && xx >= 0 && xx < Ww)
                    val = x[((b * Cc + c0 + c) << 10) + (zz << 8) + (yy << 4) + xx];
                sA[v][c] = val;
            }
            #pragma unroll
            for (int t = 0; t < 36; ++t) {
                int idx = tid + t * 128;         // 0..4607
                int o = idx / 96, c = idx % 96;
                sW[o][c] = g_w1t[tap * (48 * Cc) + o * Cc + c0 + c];
            }
            __syncthreads();
            #pragma unroll 8
            for (int c = 0; c < 96; ++c) {
                float a0 = sA[lg * 4 + 0][c], a1 = sA[lg * 4 + 1][c];
                float a2 = sA[lg * 4 + 2][c], a3 = sA[lg * 4 + 3][c];
                float w0 = sW[og * 3 + 0][c], w1v = sW[og * 3 + 1][c], w2v = sW[og * 3 + 2][c];
                acc[0][0] += a0 * w0; acc[0][1] += a0 * w1v; acc[0][2] += a0 * w2v;
                acc[1][0] += a1 * w0; acc[1][1] += a1 * w1v; acc[1][2] += a1 * w2v;
                acc[2][0] += a2 * w0; acc[2][1] += a2 * w1v; acc[2][2] += a2 * w2v;
                acc[3][0] += a3 * w0; acc[3][1] += a3 * w1v; acc[3][2] += a3 * w2v;
            }
            __syncthreads();
        }
    }
    #pragma unroll
    for (int i = 0; i < 4; ++i) {
        int v = lg * 4 + i;
        int vy = y0 + (v >> 4), vx = v & 15;
        int l = (z << 8) + (vy << 4) + vx;
        #pragma unroll
        for (int j = 0; j < 3; ++j) {
            int o = og * 3 + j;
            g_hid[((b * 48 + o) << 10) + l] = geluf_(acc[i][j] + b1[o]);
        }
    }
}

// ---------------- conv2 tiled: g_hid -> offsets [B,L,3] ----------------
// grid 256 = (b, z, y); block 144
__global__ void conv2_kernel(const float* __restrict__ w2, const float* __restrict__ b2) {
    __shared__ float sH[48 * 162];   // [c][zz(3)][yy(3)][xx(18)]
    __shared__ float red[2304];      // [j][xp][i]
    int bid = blockIdx.x;
    int b = bid >> 6, z = (bid >> 4) & 3, y = bid & 15;
    int tid = threadIdx.x;
    for (int idx = tid; idx < 48 * 162; idx += 144) {
        int c = idx / 162, r = idx % 162;
        int zz = r / 54, yy = (r / 18) % 3, xx = r % 18;
        int gz = z + zz - 1, gy = y + yy - 1, gx = xx - 1;
        float val = 0.f;
        if (gz >= 0 && gz < Dd && gy >= 0 && gy < Hh && gx >= 0 && gx < Ww)
            val = g_hid[((b * 48 + c) << 10) + (gz << 8) + (gy << 4) + gx];
        sH[idx] = val;
    }
    __syncthreads();
    int i = tid % 48, j = tid / 48;
    float wr[27];
    #pragma unroll
    for (int tap = 0; tap < 27; ++tap) wr[tap] = w2[(j * 48 + i) * 27 + tap];
    for (int xp = 0; xp < 16; ++xp) {
        float s = 0.f;
        #pragma unroll
        for (int tap = 0; tap < 27; ++tap) {
            int kd = tap / 9, kh = (tap / 3) % 3, kw = tap % 3;
            s += sH[i * 162 + kd * 54 + kh * 18 + xp + kw] * wr[tap];
        }
        red[(j * 16 + xp) * 48 + i] = s;
    }
    __syncthreads();
    if (tid < 48) {
        int jj = tid >> 4, xp = tid & 15;
        float s = b2[jj];
        #pragma unroll 8
        for (int k = 0; k < 48; ++k) s += red[(jj * 16 + xp) * 48 + k];
        g_offs[(((b << 10) + (z << 8) + (y << 4) + xp)) * 3 + jj] = s;
    }
}

// ---------------- pos-emb grid sample -> g_xs (uses g_xT, coalesced) ----------------
__global__ void posemb_kernel() {
    int bl = blockIdx.x;
    int b = bl >> 10;
    int c = threadIdx.x;
    float gx = g_offs[bl * 3 + 0];
    float gy = g_offs[bl * 3 + 1];
    float gz = g_offs[bl * 3 + 2];
    float ixf = ((gx + 1.f) * (float)Ww - 1.f) * 0.5f;
    float iyf = ((gy + 1.f) * (float)Hh - 1.f) * 0.5f;
    float izf = ((gz + 1.f) * (float)Dd - 1.f) * 0.5f;
    float x0 = floorf(ixf), y0 = floorf(iyf), z0 = floorf(izf);
    float pe = 0.f;
    #pragma unroll
    for (int dz = 0; dz < 2; ++dz)
    #pragma unroll
    for (int dy = 0; dy < 2; ++dy)
    #pragma unroll
    for (int dx = 0; dx < 2; ++dx) {
        float xc = x0 + dx, yc = y0 + dy, zc = z0 + dz;
        float wgt = (1.f - fabsf(ixf - xc)) * (1.f - fabsf(iyf - yc)) * (1.f - fabsf(izf - zc));
        bool valid = (xc >= 0.f) && (xc < (float)Ww) && (yc >= 0.f) && (yc < (float)Hh)
                  && (zc >= 0.f) && (zc < (float)Dd);
        int xi_ = (int)fminf(fmaxf(xc, 0.f), (float)(Ww - 1));
        int yi_ = (int)fminf(fmaxf(yc, 0.f), (float)(Hh - 1));
        int zi_ = (int)fminf(fmaxf(zc, 0.f), (float)(Dd - 1));
        int idx = (zi_ * Hh + yi_) * Ww + xi_;
        pe += g_xT[(b * LL + idx) * Cc + c] * wgt * (valid ? 1.f : 0.f);
    }
    g_xs[bl * Cc + c] = pe;
}

// ---------------- generic tiled GEMM: C[M][N] = A[M][K] * W[N][K]^T ----------------
// grid (M/32, ceil(N/64)); block 128; micro-tile 4x4
// EPI 0: plain store  1: xseq (+bias)*wts += g_xs   2: outproj transposed store
template<int K, int N, int EPI>
__global__ void gemm_kernel(const float* __restrict__ A, const float* __restrict__ W,
                            float* __restrict__ outp) {
    __shared__ float sA[32][65];
    __shared__ float sW[64][65];
    int m0 = blockIdx.x * 32;
    int n0 = blockIdx.y * 64;
    int tid = threadIdx.x;
    int lg = tid & 7, og = tid >> 3;
    float acc[4][4] = {};
    for (int k0 = 0; k0 < K; k0 += 64) {
        #pragma unroll
        for (int t = 0; t < 16; ++t) {
            int idx = tid + t * 128;
            int r = idx >> 6, c = idx & 63;
            sA[r][c] = A[(m0 + r) * K + k0 + c];
        }
        #pragma unroll
        for (int t = 0; t < 32; ++t) {
            int idx = tid + t * 128;
            int r = idx >> 6, c = idx & 63;
            int n = n0 + r;
            sW[r][c] = (n < N) ? W[n * K + k0 + c] : 0.f;
        }
        __syncthreads();
        #pragma unroll 16
        for (int kc = 0; kc < 64; ++kc) {
            float a0 = sA[lg * 4 + 0][kc], a1 = sA[lg * 4 + 1][kc];
            float a2 = sA[lg * 4 + 2][kc], a3 = sA[lg * 4 + 3][kc];
            float w0 = sW[og * 4 + 0][kc], w1 = sW[og * 4 + 1][kc];
            float w2 = sW[og * 4 + 2][kc], w3 = sW[og * 4 + 3][kc];
            acc[0][0] += a0 * w0; acc[0][1] += a0 * w1; acc[0][2] += a0 * w2; acc[0][3] += a0 * w3;
            acc[1][0] += a1 * w0; acc[1][1] += a1 * w1; acc[1][2] += a1 * w2; acc[1][3] += a1 * w3;
            acc[2][0] += a2 * w0; acc[2][1] += a2 * w1; acc[2][2] += a2 * w2; acc[2][3] += a2 * w3;
            acc[3][0] += a3 * w0; acc[3][1] += a3 * w1; acc[3][2] += a3 * w2; acc[3][3] += a3 * w3;
        }
        __syncthreads();
    }
    #pragma unroll
    for (int i = 0; i < 4; ++i) {
        int l = m0 + lg * 4 + i;
        #pragma unroll
        for (int j = 0; j < 4; ++j) {
            int n = n0 + og * 4 + j;
            if (n < N) {
                if (EPI == 0) {
                    outp[l * N + n] = acc[i][j];
                } else if (EPI == 1) {
                    float wt = g_wts[(l >> 10) * 3 + (n >> 6)];
                    g_xs[l * Cc + n] += (acc[i][j] + g_bcat[n]) * wt;
                } else {
                    outp[(((l >> 10) * Cc + n) << 10) + (l & 1023)] = acc[i][j];
                }
            }
        }
    }
}

// ---------------- depthwise causal conv (k=4) + silu ----------------
__global__ void dwconv_kernel(const float* __restrict__ cw, const float* __restrict__ cb) {
    int t = blockIdx.x * blockDim.x + threadIdx.x;
    if (t >= MM * DIN) return;
    int d = t % DIN; int bl = t / DIN; int l = bl % LL; int b = bl / LL;
    const float* base = g_xz + (b * LL) * (2 * DIN) + d;
    float s = cb[d];
    #pragma unroll
    for (int k = 0; k < DCONV; ++k) {
        int ll = l - (DCONV - 1) + k;
        if (ll >= 0) s += base[ll * (2 * DIN)] * cw[d * DCONV + k];
    }
    g_xi[t] = s * sigmoidf_(s);
}

// ---------------- delta = softplus(dt @ dt_proj_w.T + b), dtw staged in smem ----------------
__global__ void delta_kernel(const float* __restrict__ dtw, const float* __restrict__ dtb) {
    __shared__ float sdt[DIN * DTRANK];
    int tid = threadIdx.x;
    for (int k = tid; k < DIN * DTRANK; k += 256) sdt[k] = dtw[k];
    __syncthreads();
    int t = blockIdx.x * 256 + tid;
    if (t >= MM * DIN) return;
    int d = t % DIN; int bl = t / DIN;
    const float* row = g_dbl + bl * 140;
    float s = dtb[d];
    #pragma unroll
    for (int r = 0; r < DTRANK; ++r) s += row[r] * sdt[d * DTRANK + r];
    g_delta[t] = softplusf_(s);
}

// ---------------- A = -exp(A_log) ----------------
__global__ void a_kernel(const float* __restrict__ a_log) {
    int t = blockIdx.x * blockDim.x + threadIdx.x;
    if (t < DIN * DSTATE) g_A[t] = -expf(a_log[t]);
}

// ---------------- selective scan + silu(z) gate ----------------
__global__ void scan_kernel(const float* __restrict__ Dskip) {
    int warp = (blockIdx.x * blockDim.x + threadIdx.x) >> 5;
    int lane = threadIdx.x & 31;
    if (warp >= Bn * DIN) return;
    int b = warp / DIN, d = warp % DIN;
    float a0 = g_A[d * DSTATE + lane];
    float a1 = g_A[d * DSTATE + 32 + lane];
    float dsk = Dskip[d];
    float h0 = 0.f, h1 = 0.f;
    const float* dptr = g_delta + b * LL * DIN + d;
    const float* uptr = g_xi + b * LL * DIN + d;
    const float* dblb = g_dbl + b * LL * 140;
    const float* zptr = g_xz + b * LL * (2 * DIN) + DIN + d;
    float* yo = g_y + b * LL * DIN + d;
    #pragma unroll 4
    for (int l = 0; l < LL; ++l) {
        float dt = __ldg(dptr + l * DIN);
        float u = __ldg(uptr + l * DIN);
        const float* row = dblb + l * 140;
        float b0 = __ldg(row + 12 + lane), b1v = __ldg(row + 44 + lane);
        float c0 = __ldg(row + 76 + lane), c1 = __ldg(row + 108 + lane);
        float du = dt * u;
        h0 = __expf(dt * a0) * h0 + du * b0;
        h1 = __expf(dt * a1) * h1 + du * b1v;
        float part = h0 * c0 + h1 * c1;
        #pragma unroll
        for (int off = 16; off; off >>= 1) part += __shfl_xor_sync(0xffffffffu, part, off);
        if (lane == 0) {
            float z = __ldg(zptr + l * (2 * DIN));
            yo[l * DIN] = (part + u * dsk) * (z * sigmoidf_(z));
        }
    }
}

// ---------------- channel attention ----------------
__global__ void ca_kernel(const float* __restrict__ w1, const float* __restrict__ b1,
                          const float* __restrict__ w2, const float* __restrict__ b2) {
    int b = blockIdx.x;
    int tid = threadIdx.x;
    __shared__ float p[Cc];
    __shared__ float hid[48];
    p[tid] = g_p2[b * Cc + tid];
    __syncthreads();
    if (tid < 48) {
        const float* wr = w1 + tid * Cc;
        float s = b1[tid];
        for (int k = 0; k < Cc; ++k) s += p[k] * wr[k];
        hid[tid] = geluf_(s);
    }
    __syncthreads();
    const float* wr2 = w2 + tid * 48;
    float s = b2[tid];
    #pragma unroll
    for (int j = 0; j < 48; ++j) s += hid[j] * wr2[j];
    g_attn[b * Cc + tid] = sigmoidf_(s);
}

__global__ void scale_kernel(float* __restrict__ out) {
    int t = blockIdx.x * blockDim.x + threadIdx.x;
    if (t >= Bn * Cc * LL) return;
    out[t] *= g_attn[t / LL];
}

extern "C" void kernel_launch(void* const* d_in, const int* in_sizes, int n_in,
                              void* d_out, int out_size) {
    const float* x         = (const float*)d_in[0];
    const float* px_w      = (const float*)d_in[1];
    const float* px_b      = (const float*)d_in[2];
    const float* py_w      = (const float*)d_in[3];
    const float* py_b      = (const float*)d_in[4];
    const float* pz_w      = (const float*)d_in[5];
    const float* pz_b      = (const float*)d_in[6];
    const float* wg_w      = (const float*)d_in[7];
    const float* wg_b      = (const float*)d_in[8];
    const float* off_w1    = (const float*)d_in[9];
    const float* off_b1    = (const float*)d_in[10];
    const float* off_w2    = (const float*)d_in[11];
    const float* off_b2    = (const float*)d_in[12];
    const float* in_proj_w = (const float*)d_in[13];
    const float* conv_w    = (const float*)d_in[14];
    const float* conv_b    = (const float*)d_in[15];
    const float* x_proj_w  = (const float*)d_in[16];
    const float* dt_proj_w = (const float*)d_in[17];
    const float* dt_proj_b = (const float*)d_in[18];
    const float* A_log     = (const float*)d_in[19];
    const float* D_skip    = (const float*)d_in[20];
    const float* out_proj_w = (const float*)d_in[21];
    const float* ca_w1     = (const float*)d_in[22];
    const float* ca_b1     = (const float*)d_in[23];
    const float* ca_w2     = (const float*)d_in[24];
    const float* ca_b2     = (const float*)d_in[25];
    float* out = (float*)d_out;

    float *g_pooled_p, *g_p2_p, *g_xT_p, *g_xs_p, *g_xz_p, *g_xi_p, *g_dbl_p, *g_y_p, *g_Wcat_p;
    cudaGetSymbolAddress((void**)&g_pooled_p, g_pooled);
    cudaGetSymbolAddress((void**)&g_p2_p, g_p2);
    cudaGetSymbolAddress((void**)&g_xT_p, g_xT);
    cudaGetSymbolAddress((void**)&g_xs_p, g_xs);
    cudaGetSymbolAddress((void**)&g_xz_p, g_xz);
    cudaGetSymbolAddress((void**)&g_xi_p, g_xi);
    cudaGetSymbolAddress((void**)&g_dbl_p, g_dbl);
    cudaGetSymbolAddress((void**)&g_y_p, g_y);
    cudaGetSymbolAddress((void**)&g_Wcat_p, g_Wcat);

    xt_kernel<<<(MM * Cc + 255) / 256, 256>>>(x);
    mean_kernel<<<Bn * Cc, 256>>>(x, g_pooled_p);
    wts_kernel<<<Bn, 96>>>(wg_w, wg_b);
    w1t_kernel<<<(27 * 48 * Cc + 255) / 256, 256>>>(off_w1);
    catw_kernel<<<(Cc * Cc + 255) / 256, 256>>>(px_w, px_b, py_w, py_b, pz_w, pz_b);
    conv1_kernel<<<128, 128>>>(x, off_b1);
    conv2_kernel<<<256, 144>>>(off_w2, off_b2);
    posemb_kernel<<<MM, Cc>>>();
    gemm_kernel<Cc, Cc, 1><<<dim3(MM / 32, 3), 128>>>(g_xT_p, g_Wcat_p, g_xs_p);
    gemm_kernel<Cc, 2 * DIN, 0><<<dim3(MM / 32, 12), 128>>>(g_xs_p, in_proj_w, g_xz_p);
    dwconv_kernel<<<(MM * DIN + 255) / 256, 256>>>(conv_w, conv_b);
    gemm_kernel<DIN, 140, 0><<<dim3(MM / 32, 3), 128>>>(g_xi_p, x_proj_w, g_dbl_p);
    delta_kernel<<<(MM * DIN + 255) / 256, 256>>>(dt_proj_w, dt_proj_b);
    a_kernel<<<(DIN * DSTATE + 255) / 256, 256>>>(A_log);
    scan_kernel<<<(Bn * DIN * 32 + 127) / 128, 128>>>(D_skip);
    gemm_kernel<DIN, Cc, 2><<<dim3(MM / 32, 3), 128>>>(g_y_p, out_proj_w, out);
    mean_kernel<<<Bn * Cc, 256>>>(out, g_p2_p);
    ca_kernel<<<Bn, Cc>>>(ca_w1, ca_b1, ca_w2, ca_b2);
    scale_kernel<<<(Bn * Cc * LL + 255) / 256, 256>>>(out);
}